// round 2
// baseline (speedup 1.0000x reference)
#include <cuda_runtime.h>
#include <math.h>

// ============================================================================
// DrugInteractionAttention — seqlen-1 attention collapses to linear maps.
//   a_att    = drug_a @ M0 + c0,  b_att = drug_b @ M1 + c1   (M_i = Wv_i@Wo_i)
//   a_cross  = drug_b @ M2 + c2,  b_cross = drug_a @ M3 + c3 (value input!)
//   gate_pre = drug_a@(M3@Wg_bot) + drug_b@(M2@Wg_top) + bias_g
//   logits   = drug_a@(M3@Wc_bot) + drug_b@(M2@Wc_top) + bias_c
//   fused    = (a_att + b_att) * sigmoid(gate_pre)
// One big GEMM: [a|b] (16384x2048) @ Wbig (2048x2051)
// ============================================================================

#define D     1024
#define Bsz   16384
#define NBIG  2051      // 1024 att + 1024 gate + 3 logits
#define LDW   2052      // padded for float4 alignment

#define BM 128
#define BN 128
#define BK 16
#define PAD 132

// ---- device scratch (allocation-free rule: __device__ globals) ----
__device__ float g_M2[D * D];
__device__ float g_M3[D * D];
__device__ float g_Wbig[2048 * LDW];
__device__ float g_c[4 * D];
__device__ float g_bias[NBIG];
__device__ float g_att[(size_t)Bsz * D];
__device__ float g_gate[(size_t)Bsz * D];

struct GB {
    const float* A[4];
    const float* B[4];
    float*       C[4];
    int ldb[4];
    int ldc[4];
    int N[4];
};

// ---------------------------------------------------------------------------
// c_i = bv_i @ Wo_i + bo_i   (i = blockIdx.y in 0..3)
// ---------------------------------------------------------------------------
__global__ void compute_c_kernel(const float* __restrict__ bv,
                                 const float* __restrict__ Wo,
                                 const float* __restrict__ bo) {
    int i = blockIdx.y;
    int j = blockIdx.x * blockDim.x + threadIdx.x;
    if (j >= D) return;
    const float* bvi = bv + i * D;
    const float* Woi = Wo + (size_t)i * D * D;
    float s = bo[i * D + j];
    for (int k = 0; k < D; k++) s += bvi[k] * Woi[(size_t)k * D + j];
    g_c[i * D + j] = s;
}

// ---------------------------------------------------------------------------
// bias[0..1023]    = c0 + c1                         (att)
// bias[1024..2047] = bg + c2 @ Wg_top + c3 @ Wg_bot  (gate)
// bias[2048..2050] = bc + c2 @ Wc_top + c3 @ Wc_bot  (logits)
// ---------------------------------------------------------------------------
__global__ void compute_bias_kernel(const float* __restrict__ Wg,
                                    const float* __restrict__ bg,
                                    const float* __restrict__ Wc,
                                    const float* __restrict__ bc) {
    int idx = blockIdx.x * blockDim.x + threadIdx.x;
    if (idx >= NBIG) return;
    const float* c2 = g_c + 2 * D;
    const float* c3 = g_c + 3 * D;
    if (idx < D) {
        g_bias[idx] = g_c[idx] + g_c[D + idx];
    } else if (idx < 2 * D) {
        int j = idx - D;
        float s = bg[j];
        for (int k = 0; k < D; k++)
            s += c2[k] * Wg[(size_t)k * D + j] + c3[k] * Wg[(size_t)(D + k) * D + j];
        g_bias[idx] = s;
    } else {
        int j = idx - 2 * D;
        float s = bc[j];
        for (int k = 0; k < D; k++)
            s += c2[k] * Wc[k * 3 + j] + c3[k] * Wc[(D + k) * 3 + j];
        g_bias[idx] = s;
    }
}

// ---------------------------------------------------------------------------
// Batched tiled GEMM: C_z = A_z @ B_z  (row-major). M,K,lda shared; per-z rest.
// ---------------------------------------------------------------------------
__global__ __launch_bounds__(256) void gemm_batched(GB gb, int M, int K, int lda) {
    const int z = blockIdx.z;
    const float* A = gb.A[z];
    const float* B = gb.B[z];
    float*       C = gb.C[z];
    const int ldb = gb.ldb[z], ldc = gb.ldc[z], N = gb.N[z];

    const int bc = blockIdx.x * BN;
    if (bc >= N) return;
    const int br = blockIdx.y * BM;
    if (br >= M) return;

    __shared__ float As[BK][PAD];
    __shared__ float Bs[BK][PAD];

    const int tid = threadIdx.x;
    const int tx = tid & 15;
    const int ty = tid >> 4;

    float acc[8][8];
#pragma unroll
    for (int i = 0; i < 8; i++)
#pragma unroll
        for (int j = 0; j < 8; j++) acc[i][j] = 0.0f;

    for (int k0 = 0; k0 < K; k0 += BK) {
#pragma unroll
        for (int l = 0; l < 2; l++) {
            int idx = tid + l * 256;
            int ar = idx >> 2;
            int ac = (idx & 3) << 2;
            float4 v = *reinterpret_cast<const float4*>(
                A + (size_t)(br + ar) * lda + k0 + ac);
            As[ac + 0][ar] = v.x;
            As[ac + 1][ar] = v.y;
            As[ac + 2][ar] = v.z;
            As[ac + 3][ar] = v.w;
        }
#pragma unroll
        for (int l = 0; l < 2; l++) {
            int idx = tid + l * 256;
            int brow = idx >> 5;
            int bcol = (idx & 31) << 2;
            int gcol = bc + bcol;
            float4 v;
            if (gcol + 3 < N) {
                v = *reinterpret_cast<const float4*>(
                    B + (size_t)(k0 + brow) * ldb + gcol);
            } else {
                const float* bp = B + (size_t)(k0 + brow) * ldb;
                v.x = (gcol + 0 < N) ? bp[gcol + 0] : 0.0f;
                v.y = (gcol + 1 < N) ? bp[gcol + 1] : 0.0f;
                v.z = (gcol + 2 < N) ? bp[gcol + 2] : 0.0f;
                v.w = (gcol + 3 < N) ? bp[gcol + 3] : 0.0f;
            }
            *reinterpret_cast<float4*>(&Bs[brow][bcol]) = v;
        }
        __syncthreads();

#pragma unroll
        for (int kk = 0; kk < BK; kk++) {
            float4 a0 = *reinterpret_cast<const float4*>(&As[kk][ty * 4]);
            float4 a1 = *reinterpret_cast<const float4*>(&As[kk][64 + ty * 4]);
            float4 b0 = *reinterpret_cast<const float4*>(&Bs[kk][tx * 4]);
            float4 b1 = *reinterpret_cast<const float4*>(&Bs[kk][64 + tx * 4]);
            float ra[8] = {a0.x, a0.y, a0.z, a0.w, a1.x, a1.y, a1.z, a1.w};
            float rb[8] = {b0.x, b0.y, b0.z, b0.w, b1.x, b1.y, b1.z, b1.w};
#pragma unroll
            for (int i = 0; i < 8; i++)
#pragma unroll
                for (int j = 0; j < 8; j++) acc[i][j] += ra[i] * rb[j];
        }
        __syncthreads();
    }

#pragma unroll
    for (int i = 0; i < 8; i++) {
        int row = br + ty * 4 + (i < 4 ? i : 60 + i);
        if (row >= M) continue;
#pragma unroll
        for (int j = 0; j < 8; j++) {
            int col = bc + tx * 4 + (j < 4 ? j : 60 + j);
            if (col < N) C[(size_t)row * ldc + col] = acc[i][j];
        }
    }
}

// ---------------------------------------------------------------------------
// Main GEMM: [drug_a | drug_b] @ g_Wbig + g_bias, routed epilogue.
// ---------------------------------------------------------------------------
__global__ __launch_bounds__(256) void main_gemm(const float* __restrict__ da,
                                                 const float* __restrict__ db,
                                                 float* __restrict__ logits_out) {
    const int N = NBIG, K = 2048, lda = D, ldb = LDW;

    const int bc = blockIdx.x * BN;
    if (bc >= N) return;
    const int br = blockIdx.y * BM;

    __shared__ float As[BK][PAD];
    __shared__ float Bs[BK][PAD];

    const int tid = threadIdx.x;
    const int tx = tid & 15;
    const int ty = tid >> 4;

    float acc[8][8];
#pragma unroll
    for (int i = 0; i < 8; i++)
#pragma unroll
        for (int j = 0; j < 8; j++) acc[i][j] = 0.0f;

    for (int k0 = 0; k0 < K; k0 += BK) {
        const float* A = (k0 < D) ? da : db;
        const int kb = k0 & (D - 1);
#pragma unroll
        for (int l = 0; l < 2; l++) {
            int idx = tid + l * 256;
            int ar = idx >> 2;
            int ac = (idx & 3) << 2;
            float4 v = *reinterpret_cast<const float4*>(
                A + (size_t)(br + ar) * lda + kb + ac);
            As[ac + 0][ar] = v.x;
            As[ac + 1][ar] = v.y;
            As[ac + 2][ar] = v.z;
            As[ac + 3][ar] = v.w;
        }
#pragma unroll
        for (int l = 0; l < 2; l++) {
            int idx = tid + l * 256;
            int brow = idx >> 5;
            int bcol = (idx & 31) << 2;
            int gcol = bc + bcol;
            float4 v;
            if (gcol + 3 < N) {
                v = *reinterpret_cast<const float4*>(
                    g_Wbig + (size_t)(k0 + brow) * ldb + gcol);
            } else {
                const float* bp = g_Wbig + (size_t)(k0 + brow) * ldb;
                v.x = (gcol + 0 < N) ? bp[gcol + 0] : 0.0f;
                v.y = (gcol + 1 < N) ? bp[gcol + 1] : 0.0f;
                v.z = (gcol + 2 < N) ? bp[gcol + 2] : 0.0f;
                v.w = (gcol + 3 < N) ? bp[gcol + 3] : 0.0f;
            }
            *reinterpret_cast<float4*>(&Bs[brow][bcol]) = v;
        }
        __syncthreads();

#pragma unroll
        for (int kk = 0; kk < BK; kk++) {
            float4 a0 = *reinterpret_cast<const float4*>(&As[kk][ty * 4]);
            float4 a1 = *reinterpret_cast<const float4*>(&As[kk][64 + ty * 4]);
            float4 b0 = *reinterpret_cast<const float4*>(&Bs[kk][tx * 4]);
            float4 b1 = *reinterpret_cast<const float4*>(&Bs[kk][64 + tx * 4]);
            float ra[8] = {a0.x, a0.y, a0.z, a0.w, a1.x, a1.y, a1.z, a1.w};
            float rb[8] = {b0.x, b0.y, b0.z, b0.w, b1.x, b1.y, b1.z, b1.w};
#pragma unroll
            for (int i = 0; i < 8; i++)
#pragma unroll
                for (int j = 0; j < 8; j++) acc[i][j] += ra[i] * rb[j];
        }
        __syncthreads();
    }

#pragma unroll
    for (int i = 0; i < 8; i++) {
        int row = br + ty * 4 + (i < 4 ? i : 60 + i);
#pragma unroll
        for (int j = 0; j < 8; j++) {
            int col = bc + tx * 4 + (j < 4 ? j : 60 + j);
            if (col >= N) continue;
            float val = acc[i][j] + g_bias[col];
            if (col < D) {
                g_att[(size_t)row * D + col] = val;
            } else if (col < 2 * D) {
                g_gate[(size_t)row * D + (col - D)] = val;
            } else {
                logits_out[(size_t)row * 3 + (col - 2 * D)] = val;
            }
        }
    }
}

// ---------------------------------------------------------------------------
// fused = att * sigmoid(gate)   (float4 streaming)
// ---------------------------------------------------------------------------
__global__ void fuse_kernel(float* __restrict__ out) {
    size_t i = (size_t)blockIdx.x * blockDim.x + threadIdx.x;
    float4 a = *reinterpret_cast<const float4*>(&g_att[i * 4]);
    float4 g = *reinterpret_cast<const float4*>(&g_gate[i * 4]);
    float4 r;
    r.x = a.x / (1.0f + expf(-g.x));
    r.y = a.y / (1.0f + expf(-g.y));
    r.z = a.z / (1.0f + expf(-g.z));
    r.w = a.w / (1.0f + expf(-g.w));
    reinterpret_cast<float4*>(out)[i] = r;
}

// ---------------------------------------------------------------------------
extern "C" void kernel_launch(void* const* d_in, const int* in_sizes, int n_in,
                              void* d_out, int out_size) {
    const float* drug_a = (const float*)d_in[0];
    const float* drug_b = (const float*)d_in[1];
    const float* Wv = (const float*)d_in[6];
    const float* bv = (const float*)d_in[7];
    const float* Wo = (const float*)d_in[8];
    const float* bo = (const float*)d_in[9];
    const float* Wc = (const float*)d_in[10];
    const float* bc_ = (const float*)d_in[11];
    const float* Wg = (const float*)d_in[12];
    const float* bg = (const float*)d_in[13];
    float* out = (float*)d_out;

    float *pM2, *pM3, *pWbig;
    cudaGetSymbolAddress((void**)&pM2, g_M2);
    cudaGetSymbolAddress((void**)&pM3, g_M3);
    cudaGetSymbolAddress((void**)&pWbig, g_Wbig);

    const size_t DD = (size_t)D * D;

    // 1) composite biases c_i = bv_i @ Wo_i + bo_i
    compute_c_kernel<<<dim3(4, 4), 256>>>(bv, Wo, bo);

    // 2) M_i = Wv_i @ Wo_i   (M0,M1 straight into Wbig; M2,M3 staged)
    GB g1;
    for (int i = 0; i < 4; i++) {
        g1.A[i] = Wv + i * DD;
        g1.B[i] = Wo + i * DD;
        g1.ldb[i] = D;
        g1.N[i] = D;
    }
    g1.C[0] = pWbig;              g1.ldc[0] = LDW;
    g1.C[1] = pWbig + (size_t)D * LDW; g1.ldc[1] = LDW;
    g1.C[2] = pM2;                g1.ldc[2] = D;
    g1.C[3] = pM3;                g1.ldc[3] = D;
    gemm_batched<<<dim3(8, 8, 4), 256>>>(g1, D, D, D);

    // 3) gate / logit composites into Wbig
    GB g2;
    g2.A[0] = pM3; g2.B[0] = Wg + DD;    g2.ldb[0] = D; g2.C[0] = pWbig + D;                       g2.ldc[0] = LDW; g2.N[0] = D;
    g2.A[1] = pM2; g2.B[1] = Wg;         g2.ldb[1] = D; g2.C[1] = pWbig + (size_t)D * LDW + D;     g2.ldc[1] = LDW; g2.N[1] = D;
    g2.A[2] = pM3; g2.B[2] = Wc + D * 3; g2.ldb[2] = 3; g2.C[2] = pWbig + 2 * D;                   g2.ldc[2] = LDW; g2.N[2] = 3;
    g2.A[3] = pM2; g2.B[3] = Wc;         g2.ldb[3] = 3; g2.C[3] = pWbig + (size_t)D * LDW + 2 * D; g2.ldc[3] = LDW; g2.N[3] = 3;
    gemm_batched<<<dim3(8, 8, 4), 256>>>(g2, D, D, D);

    // 4) bias vector
    compute_bias_kernel<<<9, 256>>>(Wg, bg, Wc, bc_);

    // 5) the one big GEMM (att/gate to scratch, logits direct to out)
    main_gemm<<<dim3(17, Bsz / BM), 256>>>(drug_a, drug_b, out + (size_t)Bsz * D);

    // 6) gated fuse -> out[0 : B*D]
    fuse_kernel<<<(Bsz * D / 4) / 256, 256>>>(out);
}

// round 12
// speedup vs baseline: 1.3911x; 1.3911x over previous
#include <cuda_runtime.h>
#include <math.h>
#include <stdint.h>

// ============================================================================
// DrugInteractionAttention — seqlen-1 attention collapses to linear maps.
//   a_att   = drug_a @ M0 + c0,  b_att   = drug_b @ M1 + c1   (M_i = Wv_i@Wo_i)
//   a_cross = drug_b @ M2 + c2,  b_cross = drug_a @ M3 + c3
//   gate_pre = drug_a@(M3@Wg_bot) + drug_b@(M2@Wg_top) + bias_g
//   logits   = drug_a@(M3@Wc_bot) + drug_b@(M2@Wc_top) + bias_c
//   fused    = (a_att + b_att) * sigmoid(gate_pre)
// One big GEMM: [a|b] (16384x2048) @ Wbig (2048x2051).
// All GEMMs: TF32x3 error-compensated mma.sync (fp32-class accuracy).
// ============================================================================

#define D     1024
#define Bsz   16384
#define NBIG  2051
#define LDW   2052      // padded row stride of Wbig (float4-aligned)

#define BM 128
#define BN 128
#define BK 16
#define ASTR 20         // As row stride (floats): banks g*20+t distinct mod 32
#define BSTR 136        // Bs row stride (floats): banks (r*8+n0) distinct mod 32

// ---- device scratch ----
__device__ float g_M2[D * D];
__device__ float g_M3[D * D];
__device__ float g_Wbig[2048 * LDW];
__device__ float g_c[4 * D];
__device__ float g_bias[NBIG];
__device__ float g_att[(size_t)Bsz * D];
__device__ float g_gate[(size_t)Bsz * D];

// ---------------------------------------------------------------------------
// PTX helpers
// ---------------------------------------------------------------------------
__device__ __forceinline__ void cp16(uint32_t dst, const void* src) {
    asm volatile("cp.async.cg.shared.global [%0], [%1], 16;\n" :: "r"(dst), "l"(src));
}
__device__ __forceinline__ void cp16z(uint32_t dst, const void* src, int srcbytes) {
    asm volatile("cp.async.cg.shared.global [%0], [%1], 16, %2;\n"
                 :: "r"(dst), "l"(src), "r"(srcbytes));
}
__device__ __forceinline__ void cp_commit() { asm volatile("cp.async.commit_group;\n"); }
__device__ __forceinline__ void cp_wait1()  { asm volatile("cp.async.wait_group 1;\n"); }

__device__ __forceinline__ uint32_t f2tf32(float x) {
    uint32_t r;
    asm("cvt.rna.tf32.f32 %0, %1;\n" : "=r"(r) : "f"(x));
    return r;
}

__device__ __forceinline__ void mma_tf32(float d[4], const uint32_t a[4], const uint32_t b[2]) {
    asm volatile(
        "mma.sync.aligned.m16n8k8.row.col.f32.tf32.tf32.f32 "
        "{%0,%1,%2,%3}, {%4,%5,%6,%7}, {%8,%9}, {%0,%1,%2,%3};\n"
        : "+f"(d[0]), "+f"(d[1]), "+f"(d[2]), "+f"(d[3])
        : "r"(a[0]), "r"(a[1]), "r"(a[2]), "r"(a[3]), "r"(b[0]), "r"(b[1]));
}

// tf32x3: acc += a*b with error compensation (drops only lo*lo ~ 2^-22)
__device__ __forceinline__ void mma_tf32x3(float d[4],
                                           const uint32_t ah[4], const uint32_t al[4],
                                           const uint32_t bh[2], const uint32_t bl[2]) {
    mma_tf32(d, ah, bl);
    mma_tf32(d, al, bh);
    mma_tf32(d, ah, bh);
}

// ---------------------------------------------------------------------------
// compute_c: c_i = bv_i @ Wo_i + bo_i.  grid (32, 4), 256 thr, warp = k-slice.
// ---------------------------------------------------------------------------
__global__ void compute_c_kernel(const float* __restrict__ bv,
                                 const float* __restrict__ Wo,
                                 const float* __restrict__ bo) {
    __shared__ float red[8][32];
    int i = blockIdx.y;
    int j = blockIdx.x * 32 + (threadIdx.x & 31);
    int slice = threadIdx.x >> 5;
    const float* bvi = bv + i * D;
    const float* Woi = Wo + (size_t)i * D * D;
    float s = 0.0f;
    for (int k = slice * 128; k < slice * 128 + 128; k++)
        s += bvi[k] * Woi[(size_t)k * D + j];
    red[slice][threadIdx.x & 31] = s;
    __syncthreads();
    if (slice == 0) {
        float acc = 0.0f;
#pragma unroll
        for (int w = 0; w < 8; w++) acc += red[w][threadIdx.x & 31];
        g_c[i * D + j] = acc + bo[i * D + j];
    }
}

// ---------------------------------------------------------------------------
// compute_bias: blocks 0..31 gate chunks; block 32 att; block 33 logits.
// ---------------------------------------------------------------------------
__global__ void compute_bias_kernel(const float* __restrict__ Wg,
                                    const float* __restrict__ bg,
                                    const float* __restrict__ Wc,
                                    const float* __restrict__ bc) {
    const float* c2 = g_c + 2 * D;
    const float* c3 = g_c + 3 * D;
    int b = blockIdx.x;
    if (b < 32) {
        __shared__ float red[8][32];
        int j = b * 32 + (threadIdx.x & 31);
        int slice = threadIdx.x >> 5;
        float s = 0.0f;
        for (int k = slice * 128; k < slice * 128 + 128; k++)
            s += c2[k] * Wg[(size_t)k * D + j] + c3[k] * Wg[(size_t)(D + k) * D + j];
        red[slice][threadIdx.x & 31] = s;
        __syncthreads();
        if (slice == 0) {
            float acc = bg[j];
#pragma unroll
            for (int w = 0; w < 8; w++) acc += red[w][threadIdx.x & 31];
            g_bias[D + j] = acc;
        }
    } else if (b == 32) {
        for (int j = threadIdx.x; j < D; j += 256)
            g_bias[j] = g_c[j] + g_c[D + j];
    } else {
        int t = threadIdx.x;
        if (t < 96) {
            int j = t >> 5, l = t & 31;
            float s = 0.0f;
            for (int k = l; k < D; k += 32)
                s += c2[k] * Wc[k * 3 + j] + c3[k] * Wc[(D + k) * 3 + j];
#pragma unroll
            for (int off = 16; off > 0; off >>= 1)
                s += __shfl_down_sync(0xFFFFFFFFu, s, off);
            if (l == 0) g_bias[2 * D + j] = s + bc[j];
        }
    }
}

// ---------------------------------------------------------------------------
// logits composite columns of Wbig: cols 2048..2050.
// ---------------------------------------------------------------------------
__global__ void logits_comp_kernel(const float* __restrict__ Wc) {
    __shared__ float red[32][8][3];
    int matsel = blockIdx.x & 1;           // 0: M3 (rows 0..), 1: M2 (rows 1024..)
    int i = (blockIdx.x >> 1) * 32 + (threadIdx.x >> 3);
    int slice = threadIdx.x & 7;
    const float* A = matsel ? g_M2 : g_M3;
    int wcbase = matsel ? 0 : D;
    float p0 = 0.f, p1 = 0.f, p2 = 0.f;
    const float* arow = A + (size_t)i * D;
    for (int k = slice * 128; k < slice * 128 + 128; k++) {
        float a = arow[k];
        const float* w = Wc + (size_t)(wcbase + k) * 3;
        p0 += a * w[0]; p1 += a * w[1]; p2 += a * w[2];
    }
    int ii = threadIdx.x >> 3;
    red[ii][slice][0] = p0; red[ii][slice][1] = p1; red[ii][slice][2] = p2;
    __syncthreads();
    if (slice == 0) {
        float s0 = 0.f, s1 = 0.f, s2 = 0.f;
#pragma unroll
        for (int w = 0; w < 8; w++) {
            s0 += red[ii][w][0]; s1 += red[ii][w][1]; s2 += red[ii][w][2];
        }
        float* dst = g_Wbig + (size_t)(matsel * D + i) * LDW + 2 * D;
        dst[0] = s0; dst[1] = s1; dst[2] = s2;
    }
}

// ---------------------------------------------------------------------------
// Fragment load + split helpers (shared by both GEMMs)
// ---------------------------------------------------------------------------
#define LOAD_SPLIT_FRAGS(Asm, Bsm)                                             \
    uint32_t ah[4][4], al[4][4], bh[4][2], bl[4][2];                           \
    _Pragma("unroll")                                                          \
    for (int mt = 0; mt < 4; mt++) {                                           \
        int m0 = wm * 64 + mt * 16 + g;                                        \
        float f0 = Asm[m0][ks * 8 + t];                                        \
        float f1 = Asm[m0 + 8][ks * 8 + t];                                    \
        float f2 = Asm[m0][ks * 8 + t + 4];                                    \
        float f3 = Asm[m0 + 8][ks * 8 + t + 4];                                \
        ah[mt][0] = f2tf32(f0); al[mt][0] = f2tf32(f0 - __uint_as_float(ah[mt][0])); \
        ah[mt][1] = f2tf32(f1); al[mt][1] = f2tf32(f1 - __uint_as_float(ah[mt][1])); \
        ah[mt][2] = f2tf32(f2); al[mt][2] = f2tf32(f2 - __uint_as_float(ah[mt][2])); \
        ah[mt][3] = f2tf32(f3); al[mt][3] = f2tf32(f3 - __uint_as_float(ah[mt][3])); \
    }                                                                          \
    _Pragma("unroll")                                                          \
    for (int nt = 0; nt < 4; nt++) {                                           \
        int n0 = wn * 32 + nt * 8 + g;                                         \
        float f0 = Bsm[ks * 8 + t][n0];                                        \
        float f1 = Bsm[ks * 8 + t + 4][n0];                                    \
        bh[nt][0] = f2tf32(f0); bl[nt][0] = f2tf32(f0 - __uint_as_float(bh[nt][0])); \
        bh[nt][1] = f2tf32(f1); bl[nt][1] = f2tf32(f1 - __uint_as_float(bh[nt][1])); \
    }

// ---------------------------------------------------------------------------
// TF32x3 GEMM, batched: BM=BN=128, BK=16, 256 thr, 8 warps (2m x 4n).
// ---------------------------------------------------------------------------
struct GB4 {
    const float* A[4];
    const float* B[4];
    float*       C[4];
    int ldc[4];
};

__global__ __launch_bounds__(256, 2) void tf32_gemm_batched(GB4 gb) {
    __shared__ float As[2][BM][ASTR];
    __shared__ float Bs[2][BK][BSTR];

    const int z = blockIdx.z;
    const float* A = gb.A[z];
    const float* B = gb.B[z];
    float*       C = gb.C[z];
    const int ldc = gb.ldc[z];
    const int lda = D, ldb = D, K = D;

    const int br = blockIdx.y * BM;
    const int bc = blockIdx.x * BN;
    const int tid = threadIdx.x;
    const int wid = tid >> 5, lane = tid & 31;
    const int wm = wid & 1, wn = wid >> 1;
    const int g = lane >> 2, t = lane & 3;

    float d[4][4][4];
#pragma unroll
    for (int mt = 0; mt < 4; mt++)
#pragma unroll
        for (int nt = 0; nt < 4; nt++)
#pragma unroll
            for (int r = 0; r < 4; r++) d[mt][nt][r] = 0.0f;

    const int a_row = tid >> 2, a_c4 = tid & 3;
    const int b_row = tid >> 5, b_c4 = tid & 31;

    uint32_t sAs = (uint32_t)__cvta_generic_to_shared(&As[0][0][0]);
    uint32_t sBs = (uint32_t)__cvta_generic_to_shared(&Bs[0][0][0]);

    const int NIT = K / BK;

    {
#pragma unroll
        for (int l = 0; l < 2; l++) {
            int r = a_row + l * 64;
            cp16(sAs + (r * ASTR + a_c4 * 4) * 4, A + (size_t)(br + r) * lda + a_c4 * 4);
        }
#pragma unroll
        for (int l = 0; l < 2; l++) {
            int r = b_row + l * 8;
            cp16(sBs + (r * BSTR + b_c4 * 4) * 4, B + (size_t)r * ldb + bc + b_c4 * 4);
        }
        cp_commit();
    }

    for (int it = 0; it < NIT; it++) {
        int s = it & 1;
        if (it + 1 < NIT) {
            int k0 = (it + 1) * BK;
            int s2 = (it + 1) & 1;
            uint32_t sa = sAs + s2 * (BM * ASTR * 4);
            uint32_t sb = sBs + s2 * (BK * BSTR * 4);
#pragma unroll
            for (int l = 0; l < 2; l++) {
                int r = a_row + l * 64;
                cp16(sa + (r * ASTR + a_c4 * 4) * 4, A + (size_t)(br + r) * lda + k0 + a_c4 * 4);
            }
#pragma unroll
            for (int l = 0; l < 2; l++) {
                int r = b_row + l * 8;
                cp16(sb + (r * BSTR + b_c4 * 4) * 4, B + (size_t)(k0 + r) * ldb + bc + b_c4 * 4);
            }
        }
        cp_commit();
        cp_wait1();
        __syncthreads();

#pragma unroll
        for (int ks = 0; ks < 2; ks++) {
            LOAD_SPLIT_FRAGS(As[s], Bs[s]);
#pragma unroll
            for (int mt = 0; mt < 4; mt++)
#pragma unroll
                for (int nt = 0; nt < 4; nt++)
                    mma_tf32x3(d[mt][nt], ah[mt], al[mt], bh[nt], bl[nt]);
        }
        __syncthreads();
    }

#pragma unroll
    for (int mt = 0; mt < 4; mt++) {
#pragma unroll
        for (int nt = 0; nt < 4; nt++) {
#pragma unroll
            for (int r = 0; r < 4; r++) {
                int row = br + wm * 64 + mt * 16 + g + ((r >= 2) ? 8 : 0);
                int col = bc + wn * 32 + nt * 8 + t * 2 + (r & 1);
                C[(size_t)row * ldc + col] = d[mt][nt][r];
            }
        }
    }
}

// ---------------------------------------------------------------------------
// Main TF32x3 GEMM: [a|b] @ g_Wbig + g_bias, routed epilogue. N = 2051.
// ---------------------------------------------------------------------------
__global__ __launch_bounds__(256, 2) void main_gemm_tf32(const float* __restrict__ da,
                                                         const float* __restrict__ db,
                                                         float* __restrict__ logits_out) {
    __shared__ float As[2][BM][ASTR];
    __shared__ float Bs[2][BK][BSTR];

    const int K = 2048, lda = D, ldb = LDW, N = NBIG;
    const int br = blockIdx.y * BM;
    const int bc = blockIdx.x * BN;
    const int tid = threadIdx.x;
    const int wid = tid >> 5, lane = tid & 31;
    const int wm = wid & 1, wn = wid >> 1;
    const int g = lane >> 2, t = lane & 3;

    float d[4][4][4];
#pragma unroll
    for (int mt = 0; mt < 4; mt++)
#pragma unroll
        for (int nt = 0; nt < 4; nt++)
#pragma unroll
            for (int r = 0; r < 4; r++) d[mt][nt][r] = 0.0f;

    const int a_row = tid >> 2, a_c4 = tid & 3;
    const int b_row = tid >> 5, b_c4 = tid & 31;
    const bool tail = (bc + BN > N);

    uint32_t sAs = (uint32_t)__cvta_generic_to_shared(&As[0][0][0]);
    uint32_t sBs = (uint32_t)__cvta_generic_to_shared(&Bs[0][0][0]);

    const int NIT = K / BK;

#define PREFETCH(k0v, sv)                                                          \
    {                                                                              \
        const float* Ap = ((k0v) < D) ? da : db;                                   \
        int kb = (k0v) & (D - 1);                                                  \
        uint32_t sa = sAs + (sv) * (BM * ASTR * 4);                                \
        uint32_t sb = sBs + (sv) * (BK * BSTR * 4);                                \
        _Pragma("unroll")                                                          \
        for (int l = 0; l < 2; l++) {                                              \
            int r = a_row + l * 64;                                                \
            cp16(sa + (r * ASTR + a_c4 * 4) * 4,                                   \
                 Ap + (size_t)(br + r) * lda + kb + a_c4 * 4);                     \
        }                                                                          \
        _Pragma("unroll")                                                          \
        for (int l = 0; l < 2; l++) {                                              \
            int r = b_row + l * 8;                                                 \
            int gcol = bc + b_c4 * 4;                                              \
            const float* src = g_Wbig + (size_t)((k0v) + r) * ldb + gcol;          \
            if (!tail) {                                                           \
                cp16(sb + (r * BSTR + b_c4 * 4) * 4, src);                         \
            } else {                                                               \
                int avail = (N - gcol) * 4;                                        \
                if (avail < 0) avail = 0;                                          \
                if (avail > 16) avail = 16;                                        \
                const float* s2 = (avail > 0) ? src                                \
                                              : g_Wbig + (size_t)((k0v) + r) * ldb;\
                cp16z(sb + (r * BSTR + b_c4 * 4) * 4, s2, avail);                  \
            }                                                                      \
        }                                                                          \
    }

    PREFETCH(0, 0);
    cp_commit();

    for (int it = 0; it < NIT; it++) {
        int s = it & 1;
        if (it + 1 < NIT) {
            PREFETCH((it + 1) * BK, (it + 1) & 1);
        }
        cp_commit();
        cp_wait1();
        __syncthreads();

#pragma unroll
        for (int ks = 0; ks < 2; ks++) {
            LOAD_SPLIT_FRAGS(As[s], Bs[s]);
#pragma unroll
            for (int mt = 0; mt < 4; mt++)
#pragma unroll
                for (int nt = 0; nt < 4; nt++)
                    mma_tf32x3(d[mt][nt], ah[mt], al[mt], bh[nt], bl[nt]);
        }
        __syncthreads();
    }
#undef PREFETCH

    // routed epilogue
#pragma unroll
    for (int mt = 0; mt < 4; mt++) {
#pragma unroll
        for (int nt = 0; nt < 4; nt++) {
#pragma unroll
            for (int r = 0; r < 4; r++) {
                int row = br + wm * 64 + mt * 16 + g + ((r >= 2) ? 8 : 0);
                int col = bc + wn * 32 + nt * 8 + t * 2 + (r & 1);
                if (col >= N) continue;
                float val = d[mt][nt][r] + g_bias[col];
                if (col < D) {
                    g_att[(size_t)row * D + col] = val;
                } else if (col < 2 * D) {
                    g_gate[(size_t)row * D + (col - D)] = val;
                } else {
                    logits_out[(size_t)row * 3 + (col - 2 * D)] = val;
                }
            }
        }
    }
}

// ---------------------------------------------------------------------------
// fused = att * sigmoid(gate)
// ---------------------------------------------------------------------------
__global__ void fuse_kernel(float* __restrict__ out) {
    size_t i = (size_t)blockIdx.x * blockDim.x + threadIdx.x;
    float4 a = *reinterpret_cast<const float4*>(&g_att[i * 4]);
    float4 g = *reinterpret_cast<const float4*>(&g_gate[i * 4]);
    float4 r;
    r.x = a.x / (1.0f + __expf(-g.x));
    r.y = a.y / (1.0f + __expf(-g.y));
    r.z = a.z / (1.0f + __expf(-g.z));
    r.w = a.w / (1.0f + __expf(-g.w));
    reinterpret_cast<float4*>(out)[i] = r;
}

// ---------------------------------------------------------------------------
extern "C" void kernel_launch(void* const* d_in, const int* in_sizes, int n_in,
                              void* d_out, int out_size) {
    const float* drug_a = (const float*)d_in[0];
    const float* drug_b = (const float*)d_in[1];
    const float* Wv = (const float*)d_in[6];
    const float* bv = (const float*)d_in[7];
    const float* Wo = (const float*)d_in[8];
    const float* bo = (const float*)d_in[9];
    const float* Wc = (const float*)d_in[10];
    const float* bc_ = (const float*)d_in[11];
    const float* Wg = (const float*)d_in[12];
    const float* bg = (const float*)d_in[13];
    float* out = (float*)d_out;

    float *pM2, *pM3, *pWbig;
    cudaGetSymbolAddress((void**)&pM2, g_M2);
    cudaGetSymbolAddress((void**)&pM3, g_M3);
    cudaGetSymbolAddress((void**)&pWbig, g_Wbig);

    const size_t DD = (size_t)D * D;

    // 1) c_i = bv_i @ Wo_i + bo_i
    compute_c_kernel<<<dim3(32, 4), 256>>>(bv, Wo, bo);

    // 2) M_i = Wv_i @ Wo_i  (TF32x3). M0,M1 -> Wbig att cols; M2,M3 staged.
    GB4 g1;
    for (int i = 0; i < 4; i++) { g1.A[i] = Wv + i * DD; g1.B[i] = Wo + i * DD; }
    g1.C[0] = pWbig;                   g1.ldc[0] = LDW;
    g1.C[1] = pWbig + (size_t)D * LDW; g1.ldc[1] = LDW;
    g1.C[2] = pM2;                     g1.ldc[2] = D;
    g1.C[3] = pM3;                     g1.ldc[3] = D;
    tf32_gemm_batched<<<dim3(8, 8, 4), 256>>>(g1);

    // 3) gate composites (TF32x3) into Wbig cols D..2D
    GB4 g2;
    g2.A[0] = pM3; g2.B[0] = Wg + DD; g2.C[0] = pWbig + D;                   g2.ldc[0] = LDW;
    g2.A[1] = pM2; g2.B[1] = Wg;      g2.C[1] = pWbig + (size_t)D * LDW + D; g2.ldc[1] = LDW;
    g2.A[2] = g2.A[0]; g2.B[2] = g2.B[0]; g2.C[2] = g2.C[0]; g2.ldc[2] = LDW; // unused pad
    g2.A[3] = g2.A[1]; g2.B[3] = g2.B[1]; g2.C[3] = g2.C[1]; g2.ldc[3] = LDW; // unused pad
    tf32_gemm_batched<<<dim3(8, 8, 2), 256>>>(g2);

    // 4) logits composite cols (2048..2050) of Wbig
    logits_comp_kernel<<<64, 256>>>(Wc);

    // 5) bias vector
    compute_bias_kernel<<<34, 256>>>(Wg, bg, Wc, bc_);

    // 6) the one big GEMM
    main_gemm_tf32<<<dim3(17, Bsz / BM), 256>>>(drug_a, drug_b, out + (size_t)Bsz * D);

    // 7) gated fuse
    fuse_kernel<<<(Bsz * D / 4) / 256, 256>>>(out);
}

// round 16
// speedup vs baseline: 2.1754x; 1.5637x over previous
#include <cuda_runtime.h>
#include <cuda_bf16.h>
#include <math.h>
#include <stdint.h>

// ============================================================================
// DrugInteractionAttention — seqlen-1 attention collapses to linear maps.
//   One big GEMM: [a|b] (16384x2048) @ Wbig (2048x2051).
//   Compositions: TF32x3 mma.sync (fp32-class).
//   Main GEMM: BF16x3 m16n8k16 mma.sync (2x tensor rate vs tf32 expected).
// ============================================================================

#define D     1024
#define Bsz   16384
#define NBIG  2051
#define LDW   2052

#define BM 128
#define BN 128
#define BK 16
#define ASTR 20         // tf32 kernel A stride
#define BSTR 136        // tf32 kernel B stride
#define ASTR2 24        // bf16 kernel A stride (float2 reads conflict-free)
#define BSTR2 132       // bf16 kernel B stride (rows 2t reads conflict-free)

// ---- device scratch ----
__device__ float g_M2[D * D];
__device__ float g_M3[D * D];
__device__ float g_Wbig[2048 * LDW];
__device__ float g_c[4 * D];
__device__ float g_bias[NBIG];
__device__ float g_att[(size_t)Bsz * D];
__device__ float g_gate[(size_t)Bsz * D];

// ---------------------------------------------------------------------------
// PTX helpers
// ---------------------------------------------------------------------------
__device__ __forceinline__ void cp16(uint32_t dst, const void* src) {
    asm volatile("cp.async.cg.shared.global [%0], [%1], 16;\n" :: "r"(dst), "l"(src));
}
__device__ __forceinline__ void cp16z(uint32_t dst, const void* src, int srcbytes) {
    asm volatile("cp.async.cg.shared.global [%0], [%1], 16, %2;\n"
                 :: "r"(dst), "l"(src), "r"(srcbytes));
}
__device__ __forceinline__ void cp_commit() { asm volatile("cp.async.commit_group;\n"); }
__device__ __forceinline__ void cp_wait1()  { asm volatile("cp.async.wait_group 1;\n"); }

__device__ __forceinline__ uint32_t f2tf32(float x) {
    uint32_t r;
    asm("cvt.rna.tf32.f32 %0, %1;\n" : "=r"(r) : "f"(x));
    return r;
}

__device__ __forceinline__ void mma_tf32(float d[4], const uint32_t a[4], const uint32_t b[2]) {
    asm volatile(
        "mma.sync.aligned.m16n8k8.row.col.f32.tf32.tf32.f32 "
        "{%0,%1,%2,%3}, {%4,%5,%6,%7}, {%8,%9}, {%0,%1,%2,%3};\n"
        : "+f"(d[0]), "+f"(d[1]), "+f"(d[2]), "+f"(d[3])
        : "r"(a[0]), "r"(a[1]), "r"(a[2]), "r"(a[3]), "r"(b[0]), "r"(b[1]));
}

__device__ __forceinline__ void mma_tf32x3(float d[4],
                                           const uint32_t ah[4], const uint32_t al[4],
                                           const uint32_t bh[2], const uint32_t bl[2]) {
    mma_tf32(d, ah, bl);
    mma_tf32(d, al, bh);
    mma_tf32(d, ah, bh);
}

// bf16 m16n8k16 (2048 MACs/instr)
__device__ __forceinline__ void mma_bf16(float d[4], const uint32_t a[4], const uint32_t b[2]) {
    asm volatile(
        "mma.sync.aligned.m16n8k16.row.col.f32.bf16.bf16.f32 "
        "{%0,%1,%2,%3}, {%4,%5,%6,%7}, {%8,%9}, {%0,%1,%2,%3};\n"
        : "+f"(d[0]), "+f"(d[1]), "+f"(d[2]), "+f"(d[3])
        : "r"(a[0]), "r"(a[1]), "r"(a[2]), "r"(a[3]), "r"(b[0]), "r"(b[1]));
}

// split (x,y) into packed bf16x2 hi + lo; x -> low half (even k), y -> high half
__device__ __forceinline__ void split_pack(float x, float y, uint32_t& hi, uint32_t& lo) {
    __nv_bfloat162 h = __floats2bfloat162_rn(x, y);
    float hx = __bfloat162float(__low2bfloat16(h));
    float hy = __bfloat162float(__high2bfloat16(h));
    __nv_bfloat162 l = __floats2bfloat162_rn(x - hx, y - hy);
    hi = *reinterpret_cast<uint32_t*>(&h);
    lo = *reinterpret_cast<uint32_t*>(&l);
}

// ---------------------------------------------------------------------------
// compute_c: c_i = bv_i @ Wo_i + bo_i
// ---------------------------------------------------------------------------
__global__ void compute_c_kernel(const float* __restrict__ bv,
                                 const float* __restrict__ Wo,
                                 const float* __restrict__ bo) {
    __shared__ float red[8][32];
    int i = blockIdx.y;
    int j = blockIdx.x * 32 + (threadIdx.x & 31);
    int slice = threadIdx.x >> 5;
    const float* bvi = bv + i * D;
    const float* Woi = Wo + (size_t)i * D * D;
    float s = 0.0f;
    for (int k = slice * 128; k < slice * 128 + 128; k++)
        s += bvi[k] * Woi[(size_t)k * D + j];
    red[slice][threadIdx.x & 31] = s;
    __syncthreads();
    if (slice == 0) {
        float acc = 0.0f;
#pragma unroll
        for (int w = 0; w < 8; w++) acc += red[w][threadIdx.x & 31];
        g_c[i * D + j] = acc + bo[i * D + j];
    }
}

// ---------------------------------------------------------------------------
// compute_bias
// ---------------------------------------------------------------------------
__global__ void compute_bias_kernel(const float* __restrict__ Wg,
                                    const float* __restrict__ bg,
                                    const float* __restrict__ Wc,
                                    const float* __restrict__ bc) {
    const float* c2 = g_c + 2 * D;
    const float* c3 = g_c + 3 * D;
    int b = blockIdx.x;
    if (b < 32) {
        __shared__ float red[8][32];
        int j = b * 32 + (threadIdx.x & 31);
        int slice = threadIdx.x >> 5;
        float s = 0.0f;
        for (int k = slice * 128; k < slice * 128 + 128; k++)
            s += c2[k] * Wg[(size_t)k * D + j] + c3[k] * Wg[(size_t)(D + k) * D + j];
        red[slice][threadIdx.x & 31] = s;
        __syncthreads();
        if (slice == 0) {
            float acc = bg[j];
#pragma unroll
            for (int w = 0; w < 8; w++) acc += red[w][threadIdx.x & 31];
            g_bias[D + j] = acc;
        }
    } else if (b == 32) {
        for (int j = threadIdx.x; j < D; j += 256)
            g_bias[j] = g_c[j] + g_c[D + j];
    } else {
        int t = threadIdx.x;
        if (t < 96) {
            int j = t >> 5, l = t & 31;
            float s = 0.0f;
            for (int k = l; k < D; k += 32)
                s += c2[k] * Wc[k * 3 + j] + c3[k] * Wc[(D + k) * 3 + j];
#pragma unroll
            for (int off = 16; off > 0; off >>= 1)
                s += __shfl_down_sync(0xFFFFFFFFu, s, off);
            if (l == 0) g_bias[2 * D + j] = s + bc[j];
        }
    }
}

// ---------------------------------------------------------------------------
// logits composite columns of Wbig: cols 2048..2050.
// ---------------------------------------------------------------------------
__global__ void logits_comp_kernel(const float* __restrict__ Wc) {
    __shared__ float red[32][8][3];
    int matsel = blockIdx.x & 1;
    int i = (blockIdx.x >> 1) * 32 + (threadIdx.x >> 3);
    int slice = threadIdx.x & 7;
    const float* A = matsel ? g_M2 : g_M3;
    int wcbase = matsel ? 0 : D;
    float p0 = 0.f, p1 = 0.f, p2 = 0.f;
    const float* arow = A + (size_t)i * D;
    for (int k = slice * 128; k < slice * 128 + 128; k++) {
        float a = arow[k];
        const float* w = Wc + (size_t)(wcbase + k) * 3;
        p0 += a * w[0]; p1 += a * w[1]; p2 += a * w[2];
    }
    int ii = threadIdx.x >> 3;
    red[ii][slice][0] = p0; red[ii][slice][1] = p1; red[ii][slice][2] = p2;
    __syncthreads();
    if (slice == 0) {
        float s0 = 0.f, s1 = 0.f, s2 = 0.f;
#pragma unroll
        for (int w = 0; w < 8; w++) {
            s0 += red[ii][w][0]; s1 += red[ii][w][1]; s2 += red[ii][w][2];
        }
        float* dst = g_Wbig + (size_t)(matsel * D + i) * LDW + 2 * D;
        dst[0] = s0; dst[1] = s1; dst[2] = s2;
    }
}

// ---------------------------------------------------------------------------
// TF32x3 composition GEMMs (validated round 12) — unchanged.
// ---------------------------------------------------------------------------
#define LOAD_SPLIT_FRAGS(Asm, Bsm)                                             \
    uint32_t ah[4][4], al[4][4], bh[4][2], bl[4][2];                           \
    _Pragma("unroll")                                                          \
    for (int mt = 0; mt < 4; mt++) {                                           \
        int m0 = wm * 64 + mt * 16 + g;                                        \
        float f0 = Asm[m0][ks * 8 + t];                                        \
        float f1 = Asm[m0 + 8][ks * 8 + t];                                    \
        float f2 = Asm[m0][ks * 8 + t + 4];                                    \
        float f3 = Asm[m0 + 8][ks * 8 + t + 4];                                \
        ah[mt][0] = f2tf32(f0); al[mt][0] = f2tf32(f0 - __uint_as_float(ah[mt][0])); \
        ah[mt][1] = f2tf32(f1); al[mt][1] = f2tf32(f1 - __uint_as_float(ah[mt][1])); \
        ah[mt][2] = f2tf32(f2); al[mt][2] = f2tf32(f2 - __uint_as_float(ah[mt][2])); \
        ah[mt][3] = f2tf32(f3); al[mt][3] = f2tf32(f3 - __uint_as_float(ah[mt][3])); \
    }                                                                          \
    _Pragma("unroll")                                                          \
    for (int nt = 0; nt < 4; nt++) {                                           \
        int n0 = wn * 32 + nt * 8 + g;                                         \
        float f0 = Bsm[ks * 8 + t][n0];                                        \
        float f1 = Bsm[ks * 8 + t + 4][n0];                                    \
        bh[nt][0] = f2tf32(f0); bl[nt][0] = f2tf32(f0 - __uint_as_float(bh[nt][0])); \
        bh[nt][1] = f2tf32(f1); bl[nt][1] = f2tf32(f1 - __uint_as_float(bh[nt][1])); \
    }

struct GB4 {
    const float* A[4];
    const float* B[4];
    float*       C[4];
    int ldc[4];
};

__global__ __launch_bounds__(256, 2) void tf32_gemm_batched(GB4 gb) {
    __shared__ float As[2][BM][ASTR];
    __shared__ float Bs[2][BK][BSTR];

    const int z = blockIdx.z;
    const float* A = gb.A[z];
    const float* B = gb.B[z];
    float*       C = gb.C[z];
    const int ldc = gb.ldc[z];
    const int lda = D, ldb = D, K = D;

    const int br = blockIdx.y * BM;
    const int bc = blockIdx.x * BN;
    const int tid = threadIdx.x;
    const int wid = tid >> 5, lane = tid & 31;
    const int wm = wid & 1, wn = wid >> 1;
    const int g = lane >> 2, t = lane & 3;

    float d[4][4][4];
#pragma unroll
    for (int mt = 0; mt < 4; mt++)
#pragma unroll
        for (int nt = 0; nt < 4; nt++)
#pragma unroll
            for (int r = 0; r < 4; r++) d[mt][nt][r] = 0.0f;

    const int a_row = tid >> 2, a_c4 = tid & 3;
    const int b_row = tid >> 5, b_c4 = tid & 31;

    uint32_t sAs = (uint32_t)__cvta_generic_to_shared(&As[0][0][0]);
    uint32_t sBs = (uint32_t)__cvta_generic_to_shared(&Bs[0][0][0]);

    const int NIT = K / BK;

    {
#pragma unroll
        for (int l = 0; l < 2; l++) {
            int r = a_row + l * 64;
            cp16(sAs + (r * ASTR + a_c4 * 4) * 4, A + (size_t)(br + r) * lda + a_c4 * 4);
        }
#pragma unroll
        for (int l = 0; l < 2; l++) {
            int r = b_row + l * 8;
            cp16(sBs + (r * BSTR + b_c4 * 4) * 4, B + (size_t)r * ldb + bc + b_c4 * 4);
        }
        cp_commit();
    }

    for (int it = 0; it < NIT; it++) {
        int s = it & 1;
        if (it + 1 < NIT) {
            int k0 = (it + 1) * BK;
            int s2 = (it + 1) & 1;
            uint32_t sa = sAs + s2 * (BM * ASTR * 4);
            uint32_t sb = sBs + s2 * (BK * BSTR * 4);
#pragma unroll
            for (int l = 0; l < 2; l++) {
                int r = a_row + l * 64;
                cp16(sa + (r * ASTR + a_c4 * 4) * 4, A + (size_t)(br + r) * lda + k0 + a_c4 * 4);
            }
#pragma unroll
            for (int l = 0; l < 2; l++) {
                int r = b_row + l * 8;
                cp16(sb + (r * BSTR + b_c4 * 4) * 4, B + (size_t)(k0 + r) * ldb + bc + b_c4 * 4);
            }
        }
        cp_commit();
        cp_wait1();
        __syncthreads();

#pragma unroll
        for (int ks = 0; ks < 2; ks++) {
            LOAD_SPLIT_FRAGS(As[s], Bs[s]);
#pragma unroll
            for (int mt = 0; mt < 4; mt++)
#pragma unroll
                for (int nt = 0; nt < 4; nt++)
                    mma_tf32x3(d[mt][nt], ah[mt], al[mt], bh[nt], bl[nt]);
        }
        __syncthreads();
    }

#pragma unroll
    for (int mt = 0; mt < 4; mt++) {
#pragma unroll
        for (int nt = 0; nt < 4; nt++) {
#pragma unroll
            for (int r = 0; r < 4; r++) {
                int row = br + wm * 64 + mt * 16 + g + ((r >= 2) ? 8 : 0);
                int col = bc + wn * 32 + nt * 8 + t * 2 + (r & 1);
                C[(size_t)row * ldc + col] = d[mt][nt][r];
            }
        }
    }
}

// ---------------------------------------------------------------------------
// Main GEMM, BF16x3 m16n8k16: [a|b] @ g_Wbig + g_bias, routed epilogue.
// ---------------------------------------------------------------------------
__global__ __launch_bounds__(256, 2) void main_gemm_bf16(const float* __restrict__ da,
                                                         const float* __restrict__ db,
                                                         float* __restrict__ logits_out) {
    __shared__ float As[2][BM][ASTR2];
    __shared__ float Bs[2][BK][BSTR2];

    const int K = 2048, lda = D, ldb = LDW, N = NBIG;
    const int br = blockIdx.y * BM;
    const int bc = blockIdx.x * BN;
    const int tid = threadIdx.x;
    const int wid = tid >> 5, lane = tid & 31;
    const int wm = wid & 1, wn = wid >> 1;
    const int g = lane >> 2, t = lane & 3;

    float d[4][4][4];
#pragma unroll
    for (int mt = 0; mt < 4; mt++)
#pragma unroll
        for (int nt = 0; nt < 4; nt++)
#pragma unroll
            for (int r = 0; r < 4; r++) d[mt][nt][r] = 0.0f;

    const int a_row = tid >> 2, a_c4 = tid & 3;
    const int b_row = tid >> 5, b_c4 = tid & 31;
    const bool tail = (bc + BN > N);

    uint32_t sAs = (uint32_t)__cvta_generic_to_shared(&As[0][0][0]);
    uint32_t sBs = (uint32_t)__cvta_generic_to_shared(&Bs[0][0][0]);

    const int NIT = K / BK;

#define PREFETCH(k0v, sv)                                                          \
    {                                                                              \
        const float* Ap = ((k0v) < D) ? da : db;                                   \
        int kb = (k0v) & (D - 1);                                                  \
        uint32_t sa = sAs + (sv) * (BM * ASTR2 * 4);                               \
        uint32_t sb = sBs + (sv) * (BK * BSTR2 * 4);                               \
        _Pragma("unroll")                                                          \
        for (int l = 0; l < 2; l++) {                                              \
            int r = a_row + l * 64;                                                \
            cp16(sa + (r * ASTR2 + a_c4 * 4) * 4,                                  \
                 Ap + (size_t)(br + r) * lda + kb + a_c4 * 4);                     \
        }                                                                          \
        _Pragma("unroll")                                                          \
        for (int l = 0; l < 2; l++) {                                              \
            int r = b_row + l * 8;                                                 \
            int gcol = bc + b_c4 * 4;                                              \
            const float* src = g_Wbig + (size_t)((k0v) + r) * ldb + gcol;          \
            if (!tail) {                                                           \
                cp16(sb + (r * BSTR2 + b_c4 * 4) * 4, src);                        \
            } else {                                                               \
                int avail = (N - gcol) * 4;                                        \
                if (avail < 0) avail = 0;                                          \
                if (avail > 16) avail = 16;                                        \
                const float* s2 = (avail > 0) ? src                                \
                                              : g_Wbig + (size_t)((k0v) + r) * ldb;\
                cp16z(sb + (r * BSTR2 + b_c4 * 4) * 4, s2, avail);                 \
            }                                                                      \
        }                                                                          \
    }

    PREFETCH(0, 0);
    cp_commit();

    for (int it = 0; it < NIT; it++) {
        int s = it & 1;
        if (it + 1 < NIT) {
            PREFETCH((it + 1) * BK, (it + 1) & 1);
        }
        cp_commit();
        cp_wait1();
        __syncthreads();

        // --- B fragments: rows {2t,2t+1} and {2t+8,2t+9}, col n0, split+pack ---
        uint32_t bh[4][2], bl[4][2];
#pragma unroll
        for (int nt = 0; nt < 4; nt++) {
            int n0 = wn * 32 + nt * 8 + g;
            float x0 = Bs[s][2 * t][n0];
            float x1 = Bs[s][2 * t + 1][n0];
            split_pack(x0, x1, bh[nt][0], bl[nt][0]);
            float x2 = Bs[s][2 * t + 8][n0];
            float x3 = Bs[s][2 * t + 9][n0];
            split_pack(x2, x3, bh[nt][1], bl[nt][1]);
        }

        // --- A fragments per mt (staged to limit live registers) ---
#pragma unroll
        for (int mt = 0; mt < 4; mt++) {
            int m0 = wm * 64 + mt * 16 + g;
            float2 p0 = *reinterpret_cast<const float2*>(&As[s][m0][2 * t]);
            float2 p1 = *reinterpret_cast<const float2*>(&As[s][m0 + 8][2 * t]);
            float2 p2 = *reinterpret_cast<const float2*>(&As[s][m0][2 * t + 8]);
            float2 p3 = *reinterpret_cast<const float2*>(&As[s][m0 + 8][2 * t + 8]);
            uint32_t ah[4], al[4];
            split_pack(p0.x, p0.y, ah[0], al[0]);
            split_pack(p1.x, p1.y, ah[1], al[1]);
            split_pack(p2.x, p2.y, ah[2], al[2]);
            split_pack(p3.x, p3.y, ah[3], al[3]);
#pragma unroll
            for (int nt = 0; nt < 4; nt++) {
                mma_bf16(d[mt][nt], ah, bl[nt]);
                mma_bf16(d[mt][nt], al, bh[nt]);
                mma_bf16(d[mt][nt], ah, bh[nt]);
            }
        }
        __syncthreads();
    }
#undef PREFETCH

    // routed epilogue (c-fragment layout identical to tf32 variant)
#pragma unroll
    for (int mt = 0; mt < 4; mt++) {
#pragma unroll
        for (int nt = 0; nt < 4; nt++) {
#pragma unroll
            for (int r = 0; r < 4; r++) {
                int row = br + wm * 64 + mt * 16 + g + ((r >= 2) ? 8 : 0);
                int col = bc + wn * 32 + nt * 8 + t * 2 + (r & 1);
                if (col >= N) continue;
                float val = d[mt][nt][r] + g_bias[col];
                if (col < D) {
                    g_att[(size_t)row * D + col] = val;
                } else if (col < 2 * D) {
                    g_gate[(size_t)row * D + (col - D)] = val;
                } else {
                    logits_out[(size_t)row * 3 + (col - 2 * D)] = val;
                }
            }
        }
    }
}

// ---------------------------------------------------------------------------
// fused = att * sigmoid(gate)
// ---------------------------------------------------------------------------
__global__ void fuse_kernel(float* __restrict__ out) {
    size_t i = (size_t)blockIdx.x * blockDim.x + threadIdx.x;
    float4 a = *reinterpret_cast<const float4*>(&g_att[i * 4]);
    float4 g = *reinterpret_cast<const float4*>(&g_gate[i * 4]);
    float4 r;
    r.x = a.x / (1.0f + __expf(-g.x));
    r.y = a.y / (1.0f + __expf(-g.y));
    r.z = a.z / (1.0f + __expf(-g.z));
    r.w = a.w / (1.0f + __expf(-g.w));
    reinterpret_cast<float4*>(out)[i] = r;
}

// ---------------------------------------------------------------------------
extern "C" void kernel_launch(void* const* d_in, const int* in_sizes, int n_in,
                              void* d_out, int out_size) {
    const float* drug_a = (const float*)d_in[0];
    const float* drug_b = (const float*)d_in[1];
    const float* Wv = (const float*)d_in[6];
    const float* bv = (const float*)d_in[7];
    const float* Wo = (const float*)d_in[8];
    const float* bo = (const float*)d_in[9];
    const float* Wc = (const float*)d_in[10];
    const float* bc_ = (const float*)d_in[11];
    const float* Wg = (const float*)d_in[12];
    const float* bg = (const float*)d_in[13];
    float* out = (float*)d_out;

    float *pM2, *pM3, *pWbig;
    cudaGetSymbolAddress((void**)&pM2, g_M2);
    cudaGetSymbolAddress((void**)&pM3, g_M3);
    cudaGetSymbolAddress((void**)&pWbig, g_Wbig);

    const size_t DD = (size_t)D * D;

    // 1) c_i = bv_i @ Wo_i + bo_i
    compute_c_kernel<<<dim3(32, 4), 256>>>(bv, Wo, bo);

    // 2) M_i = Wv_i @ Wo_i  (TF32x3). M0,M1 -> Wbig att cols; M2,M3 staged.
    GB4 g1;
    for (int i = 0; i < 4; i++) { g1.A[i] = Wv + i * DD; g1.B[i] = Wo + i * DD; }
    g1.C[0] = pWbig;                   g1.ldc[0] = LDW;
    g1.C[1] = pWbig + (size_t)D * LDW; g1.ldc[1] = LDW;
    g1.C[2] = pM2;                     g1.ldc[2] = D;
    g1.C[3] = pM3;                     g1.ldc[3] = D;
    tf32_gemm_batched<<<dim3(8, 8, 4), 256>>>(g1);

    // 3) gate composites (TF32x3) into Wbig cols D..2D
    GB4 g2;
    g2.A[0] = pM3; g2.B[0] = Wg + DD; g2.C[0] = pWbig + D;                   g2.ldc[0] = LDW;
    g2.A[1] = pM2; g2.B[1] = Wg;      g2.C[1] = pWbig + (size_t)D * LDW + D; g2.ldc[1] = LDW;
    g2.A[2] = g2.A[0]; g2.B[2] = g2.B[0]; g2.C[2] = g2.C[0]; g2.ldc[2] = LDW; // unused pad
    g2.A[3] = g2.A[1]; g2.B[3] = g2.B[1]; g2.C[3] = g2.C[1]; g2.ldc[3] = LDW; // unused pad
    tf32_gemm_batched<<<dim3(8, 8, 2), 256>>>(g2);

    // 4) logits composite cols (2048..2050) of Wbig
    logits_comp_kernel<<<64, 256>>>(Wc);

    // 5) bias vector
    compute_bias_kernel<<<34, 256>>>(Wg, bg, Wc, bc_);

    // 6) the one big GEMM (BF16x3)
    main_gemm_bf16<<<dim3(17, Bsz / BM), 256>>>(drug_a, drug_b, out + (size_t)Bsz * D);

    // 7) gated fuse
    fuse_kernel<<<(Bsz * D / 4) / 256, 256>>>(out);
}